// round 11
// baseline (speedup 1.0000x reference)
#include <cuda_runtime.h>
#include <cuda_fp16.h>
#include <cstdint>

#define NROWS 16384
#define NCODE 8192
#define DDIM  512
#define NTILE 128
#define NTILES (NCODE / NTILE)   /* 64 */

__device__ __half g_xh[(size_t)NROWS * DDIM];
__device__ __half g_eh[(size_t)NCODE * DDIM];
__device__ unsigned g_tmax[(size_t)NROWS * NTILES];   // order-mapped floats; 0 = identity

// ---------------- helpers ----------------
static __device__ __forceinline__ uint32_t smem_u32(const void* p) {
    uint32_t a;
    asm("{ .reg .u64 t; cvta.to.shared.u64 t, %1; cvt.u32.u64 %0, t; }" : "=r"(a) : "l"(p));
    return a;
}
static __device__ __forceinline__ void cp16(uint32_t dst, const void* src) {
    asm volatile("cp.async.cg.shared.global [%0], [%1], 16;"
                 :: "r"(dst), "l"(__cvta_generic_to_global(src)));
}
static __device__ __forceinline__ void ldsm_x4(uint32_t* r, uint32_t addr) {
    asm volatile("ldmatrix.sync.aligned.m8n8.x4.shared.b16 {%0,%1,%2,%3}, [%4];"
                 : "=r"(r[0]), "=r"(r[1]), "=r"(r[2]), "=r"(r[3]) : "r"(addr));
}
static __device__ __forceinline__ void mma16816(float* d, const uint32_t* a, const uint32_t* b) {
    asm volatile(
        "mma.sync.aligned.m16n8k16.row.col.f32.f16.f16.f32 "
        "{%0,%1,%2,%3},{%4,%5,%6,%7},{%8,%9},{%0,%1,%2,%3};"
        : "+f"(d[0]), "+f"(d[1]), "+f"(d[2]), "+f"(d[3])
        : "r"(a[0]), "r"(a[1]), "r"(a[2]), "r"(a[3]), "r"(b[0]), "r"(b[1]));
}
static __device__ __forceinline__ unsigned fmap(float v) {
    int i = __float_as_int(v);
    return (unsigned)i ^ (unsigned)((i >> 31) | 0x80000000);
}
static __device__ __forceinline__ float funmap(unsigned k) {
    int i = (k & 0x80000000u) ? (int)(k ^ 0x80000000u) : (int)~k;
    return __int_as_float(i);
}

// ---------------- normalize rows -> f16 (+ clear g_tmax) ----------------
__global__ __launch_bounds__(128) void k_norm(const float* __restrict__ x,
                                              const float* __restrict__ e) {
    const int b = blockIdx.x, tid = threadIdx.x;
    const float* in;
    __half* out;
    if (b < NROWS) {
        in = x + (size_t)b * DDIM; out = g_xh + (size_t)b * DDIM;
        if (tid < NTILES) g_tmax[(size_t)b * NTILES + tid] = 0u;
    } else {
        in = e + (size_t)(b - NROWS) * DDIM; out = g_eh + (size_t)(b - NROWS) * DDIM;
    }
    const float4 v = ((const float4*)in)[tid];
    float ss = v.x * v.x + v.y * v.y + v.z * v.z + v.w * v.w;
    #pragma unroll
    for (int o = 16; o; o >>= 1) ss += __shfl_down_sync(0xffffffffu, ss, o);
    __shared__ float sred[4];
    if ((tid & 31) == 0) sred[tid >> 5] = ss;
    __syncthreads();
    if (tid == 0) {
        float t = sred[0] + sred[1] + sred[2] + sred[3];
        sred[0] = 1.0f / fmaxf(sqrtf(t), 1e-12f);
    }
    __syncthreads();
    const float sc = sred[0];
    __half2* oh = (__half2*)out;
    oh[tid * 2]     = __floats2half2_rn(v.x * sc, v.y * sc);
    oh[tid * 2 + 1] = __floats2half2_rn(v.z * sc, v.w * sc);
}

// ---------------- mma.sync GEMM: dist = Xn @ En^T ----------------
// CTA 128x128, 128 threads (2x2 warps, warp tile 64x64), 2-stage pipeline,
// 3 CTAs/SM target. ldsm traffic 128 B/MMA (vs 192 for 64x32 warps).
#define T_BYTES (128 * 128)
#define STG_BYTES (2 * T_BYTES)         /* 32 KB per stage */
#define GEMM_SMEM (2 * STG_BYTES)       /* 64 KB */

static __device__ __forceinline__ void load_chunk(uint32_t abase, uint32_t bbase,
                                                  int m0, int n0, int k0, int tid) {
    #pragma unroll
    for (int i = 0; i < 8; i++) {
        int idx = tid + (i << 7);
        int row = idx >> 3, g = idx & 7;
        uint32_t dst = (uint32_t)(row * 128) + ((uint32_t)(g ^ (row & 7)) << 4);
        cp16(abase + dst, g_xh + (size_t)(m0 + row) * DDIM + k0 + g * 8);
        cp16(bbase + dst, g_eh + (size_t)(n0 + row) * DDIM + k0 + g * 8);
    }
    asm volatile("cp.async.commit_group;" ::: "memory");
}

__global__ __launch_bounds__(128, 3) void k_gemm(float* __restrict__ D) {
    extern __shared__ char smem[];
    const uint32_t sb = smem_u32(smem);
    const int tid = threadIdx.x, wid = tid >> 5, lane = tid & 31;
    const int n0 = blockIdx.x << 7, m0 = blockIdx.y << 7;
    const int wm = (wid >> 1) << 6;       // 0 or 64
    const int wn = (wid & 1) << 6;        // 0 or 64

    load_chunk(sb, sb + T_BYTES, m0, n0, 0, tid);

    float acc[4][8][4];
    #pragma unroll
    for (int im = 0; im < 4; im++)
        #pragma unroll
        for (int jn = 0; jn < 8; jn++)
            #pragma unroll
            for (int q = 0; q < 4; q++) acc[im][jn][q] = 0.f;

    const int a_row = wm + (lane & 15);
    const int a_hi  = lane >> 4;
    const int b_row = wn + (lane & 7) + (((lane >> 4) & 1) << 3);
    const int b_hi  = (lane >> 3) & 1;

    #pragma unroll 1
    for (int i = 0; i < 8; i++) {
        asm volatile("cp.async.wait_group 0;" ::: "memory");
        __syncthreads();
        if (i + 1 < 8)
            load_chunk(sb + ((i + 1) & 1) * STG_BYTES,
                       sb + ((i + 1) & 1) * STG_BYTES + T_BYTES, m0, n0, (i + 1) * 64, tid);
        const uint32_t abase = sb + (i & 1) * STG_BYTES;
        const uint32_t bbase = abase + T_BYTES;
        #pragma unroll
        for (int ks = 0; ks < 4; ks++) {
            uint32_t af[4][4];
            #pragma unroll
            for (int im = 0; im < 4; im++) {
                int row = a_row + im * 16;
                uint32_t col = (uint32_t)((ks * 2 + a_hi) ^ (row & 7)) << 4;
                ldsm_x4(af[im], abase + row * 128 + col);
            }
            #pragma unroll
            for (int half = 0; half < 2; half++) {   // B in two halves -> fewer live regs
                uint32_t bf[4][2];
                #pragma unroll
                for (int p = 0; p < 2; p++) {
                    int ng = half * 2 + p;
                    int row = b_row + ng * 16;
                    uint32_t col = (uint32_t)((ks * 2 + b_hi) ^ (row & 7)) << 4;
                    uint32_t t[4];
                    ldsm_x4(t, bbase + row * 128 + col);
                    bf[2 * p][0] = t[0]; bf[2 * p][1] = t[1];
                    bf[2 * p + 1][0] = t[2]; bf[2 * p + 1][1] = t[3];
                }
                #pragma unroll
                for (int im = 0; im < 4; im++)
                    #pragma unroll
                    for (int j = 0; j < 4; j++)
                        mma16816(acc[im][half * 4 + j], af[im], bf[j]);
            }
        }
    }

    // ---- dist stores ----
    const int g = lane >> 2, tig = lane & 3;
    float* dbase = D + (size_t)(m0 + wm + g) * NCODE + n0 + wn + tig * 2;
    #pragma unroll
    for (int im = 0; im < 4; im++) {
        #pragma unroll
        for (int jn = 0; jn < 8; jn++) {
            float* p = dbase + (size_t)(im * 16) * NCODE + jn * 8;
            *(float2*)p                       = make_float2(acc[im][jn][0], acc[im][jn][1]);
            *(float2*)(p + (size_t)8 * NCODE) = make_float2(acc[im][jn][2], acc[im][jn][3]);
        }
    }

    // ---- tmax via RED.MAX: no smem, no syncs ----
    #pragma unroll
    for (int im = 0; im < 4; im++) {
        #pragma unroll
        for (int h = 0; h < 2; h++) {
            float v = -1e30f;
            #pragma unroll
            for (int jn = 0; jn < 8; jn++)
                v = fmaxf(v, fmaxf(acc[im][jn][2 * h], acc[im][jn][2 * h + 1]));
            v = fmaxf(v, __shfl_xor_sync(0xffffffffu, v, 1));
            v = fmaxf(v, __shfl_xor_sync(0xffffffffu, v, 2));
            if (tig == 0)
                atomicMax(&g_tmax[(size_t)(m0 + wm + im * 16 + h * 8 + g) * NTILES + blockIdx.x],
                          fmap(v));
        }
    }
}

// ---------------- refine ----------------
#define MAXC 128
__global__ __launch_bounds__(256) void k_refine(
    const float* __restrict__ dist, const float* __restrict__ x,
    const float* __restrict__ e, float* __restrict__ qout, float* __restrict__ iout) {
    const int r = blockIdx.x, tid = threadIdx.x;
    const int lane = tid & 31, wid = tid >> 5;

    __shared__ float tmaxs[NTILES];
    __shared__ float thr_s;
    __shared__ int clist[MAXC];
    __shared__ int ccnt;
    if (tid < NTILES) tmaxs[tid] = funmap(g_tmax[(size_t)r * NTILES + tid]);
    __syncthreads();
    if (tid < 32) {
        float v = fmaxf(tmaxs[tid], tmaxs[tid + 32]);
        #pragma unroll
        for (int o = 16; o; o >>= 1) v = fmaxf(v, __shfl_xor_sync(0xffffffffu, v, o));
        if (tid == 0) { thr_s = v - 0.005f; ccnt = 0; }
    }
    __syncthreads();
    const float thr = thr_s;

    const float* drow = dist + (size_t)r * NCODE;
    for (int t = 0; t < NTILES; t++) {
        if (tmaxs[t] >= thr && tid < NTILE) {
            float v = drow[t * NTILE + tid];
            if (v >= thr) {
                int p = atomicAdd(&ccnt, 1);
                if (p < MAXC) clist[p] = t * NTILE + tid;
            }
        }
    }
    __syncthreads();
    const int nc = min(ccnt, MAXC);

    __shared__ double cval[MAXC];
    __shared__ float cinv[MAXC];
    const float* xr = x + (size_t)r * DDIM;
    for (int cI = wid; cI < nc; cI += 8) {
        const float* er = e + (size_t)clist[cI] * DDIM;
        float s = 0.f, comp = 0.f, es = 0.f, ecomp = 0.f;
        for (int k = lane; k < DDIM; k += 32) {
            float a = xr[k], b = er[k];
            float p = __fmul_rn(a, b);
            float pe = __fmaf_rn(a, b, -p);
            float t = __fadd_rn(s, p);
            float z = __fsub_rn(t, s);
            comp = __fadd_rn(comp, __fadd_rn(__fsub_rn(s, __fsub_rn(t, z)), __fsub_rn(p, z)));
            s = t; comp = __fadd_rn(comp, pe);
            float q2 = __fmul_rn(b, b);
            float qe = __fmaf_rn(b, b, -q2);
            float t2 = __fadd_rn(es, q2);
            float z2 = __fsub_rn(t2, es);
            ecomp = __fadd_rn(ecomp, __fadd_rn(__fsub_rn(es, __fsub_rn(t2, z2)), __fsub_rn(q2, z2)));
            es = t2; ecomp = __fadd_rn(ecomp, qe);
        }
        double ds = (double)s + (double)comp;
        double de = (double)es + (double)ecomp;
        #pragma unroll
        for (int o = 16; o; o >>= 1) {
            ds += __shfl_down_sync(0xffffffffu, ds, o);
            de += __shfl_down_sync(0xffffffffu, de, o);
        }
        if (lane == 0) {
            double ne = sqrt(de);
            cval[cI] = ds / ne;
            cinv[cI] = (float)(1.0 / (ne > 1e-12 ? ne : 1e-12));
        }
    }
    __syncthreads();
    __shared__ int wcol_s;
    __shared__ float winv_s;
    if (tid == 0) {
        double best = -1e300; int bc = 0x7fffffff; float bi = 0.f;
        for (int c = 0; c < nc; c++) {
            double v = cval[c]; int col = clist[c];
            if (v > best || (v == best && col < bc)) { best = v; bc = col; bi = cinv[c]; }
        }
        wcol_s = bc; winv_s = bi;
        iout[r] = (float)bc;
    }
    __syncthreads();
    const float* ew = e + (size_t)wcol_s * DDIM;
    const float wi = winv_s;
    qout[(size_t)r * DDIM + tid]       = ew[tid] * wi;
    qout[(size_t)r * DDIM + tid + 256] = ew[tid + 256] * wi;
}

// ---------------- launch ----------------
extern "C" void kernel_launch(void* const* d_in, const int* in_sizes, int n_in,
                              void* d_out, int out_size) {
    (void)in_sizes; (void)n_in; (void)out_size;
    const float* x = (const float*)d_in[0];
    const float* e = (const float*)d_in[1];
    float* qout = (float*)d_out;
    float* iout = qout + (size_t)NROWS * DDIM;
    float* dist = iout + NROWS;

    cudaFuncSetAttribute(k_gemm, cudaFuncAttributeMaxDynamicSharedMemorySize, GEMM_SMEM);
    k_norm<<<NROWS + NCODE, 128>>>(x, e);
    dim3 gg(NCODE / 128, NROWS / 128);
    k_gemm<<<gg, 128, GEMM_SMEM>>>(dist);
    k_refine<<<NROWS, 256>>>(dist, x, e, qout, iout);
}

// round 12
// speedup vs baseline: 1.1000x; 1.1000x over previous
#include <cuda_runtime.h>
#include <cuda_fp16.h>
#include <cstdint>

#define NROWS 16384
#define NCODE 8192
#define DDIM  512
#define NTILE 128
#define NTILES (NCODE / NTILE)   /* 64 */

__device__ __half g_xh[(size_t)NROWS * DDIM];
__device__ __half g_eh[(size_t)NCODE * DDIM];
__device__ unsigned g_tmax[(size_t)NROWS * NTILES];   // order-mapped floats; 0 = identity

// ---------------- helpers ----------------
static __device__ __forceinline__ uint32_t smem_u32(const void* p) {
    uint32_t a;
    asm("{ .reg .u64 t; cvta.to.shared.u64 t, %1; cvt.u32.u64 %0, t; }" : "=r"(a) : "l"(p));
    return a;
}
static __device__ __forceinline__ void cp16(uint32_t dst, const void* src) {
    asm volatile("cp.async.cg.shared.global [%0], [%1], 16;"
                 :: "r"(dst), "l"(__cvta_generic_to_global(src)));
}
static __device__ __forceinline__ void ldsm_x4(uint32_t* r, uint32_t addr) {
    asm volatile("ldmatrix.sync.aligned.m8n8.x4.shared.b16 {%0,%1,%2,%3}, [%4];"
                 : "=r"(r[0]), "=r"(r[1]), "=r"(r[2]), "=r"(r[3]) : "r"(addr));
}
// f16 accumulator MMA: halves register pressure vs f32 acc
static __device__ __forceinline__ void mma16816h(uint32_t* d, const uint32_t* a, const uint32_t* b) {
    asm volatile(
        "mma.sync.aligned.m16n8k16.row.col.f16.f16.f16.f16 "
        "{%0,%1},{%2,%3,%4,%5},{%6,%7},{%0,%1};"
        : "+r"(d[0]), "+r"(d[1])
        : "r"(a[0]), "r"(a[1]), "r"(a[2]), "r"(a[3]), "r"(b[0]), "r"(b[1]));
}
static __device__ __forceinline__ unsigned fmap(float v) {
    int i = __float_as_int(v);
    return (unsigned)i ^ (unsigned)((i >> 31) | 0x80000000);
}
static __device__ __forceinline__ float funmap(unsigned k) {
    int i = (k & 0x80000000u) ? (int)(k ^ 0x80000000u) : (int)~k;
    return __int_as_float(i);
}

// ---------------- normalize rows -> f16 (+ clear g_tmax) ----------------
__global__ __launch_bounds__(128) void k_norm(const float* __restrict__ x,
                                              const float* __restrict__ e) {
    const int b = blockIdx.x, tid = threadIdx.x;
    const float* in;
    __half* out;
    if (b < NROWS) {
        in = x + (size_t)b * DDIM; out = g_xh + (size_t)b * DDIM;
        if (tid < NTILES) g_tmax[(size_t)b * NTILES + tid] = 0u;
    } else {
        in = e + (size_t)(b - NROWS) * DDIM; out = g_eh + (size_t)(b - NROWS) * DDIM;
    }
    const float4 v = ((const float4*)in)[tid];
    float ss = v.x * v.x + v.y * v.y + v.z * v.z + v.w * v.w;
    #pragma unroll
    for (int o = 16; o; o >>= 1) ss += __shfl_down_sync(0xffffffffu, ss, o);
    __shared__ float sred[4];
    if ((tid & 31) == 0) sred[tid >> 5] = ss;
    __syncthreads();
    if (tid == 0) {
        float t = sred[0] + sred[1] + sred[2] + sred[3];
        sred[0] = 1.0f / fmaxf(sqrtf(t), 1e-12f);
    }
    __syncthreads();
    const float sc = sred[0];
    __half2* oh = (__half2*)out;
    oh[tid * 2]     = __floats2half2_rn(v.x * sc, v.y * sc);
    oh[tid * 2 + 1] = __floats2half2_rn(v.z * sc, v.w * sc);
}

// ---------------- mma.sync GEMM (f16 acc): dist = Xn @ En^T ----------------
// CTA 128x128, 128 threads (2x2 warps, warp 64x64), 2-stage, 3 CTAs/SM,
// register double-buffered fragments. acc = 64 regs (f16x2).
#define T_BYTES (128 * 128)
#define STG_BYTES (2 * T_BYTES)         /* 32 KB per stage */
#define GEMM_SMEM (2 * STG_BYTES)       /* 64 KB */

static __device__ __forceinline__ void load_chunk(uint32_t abase, uint32_t bbase,
                                                  int m0, int n0, int k0, int tid) {
    #pragma unroll
    for (int i = 0; i < 8; i++) {
        int idx = tid + (i << 7);
        int row = idx >> 3, g = idx & 7;
        uint32_t dst = (uint32_t)(row * 128) + ((uint32_t)(g ^ (row & 7)) << 4);
        cp16(abase + dst, g_xh + (size_t)(m0 + row) * DDIM + k0 + g * 8);
        cp16(bbase + dst, g_eh + (size_t)(n0 + row) * DDIM + k0 + g * 8);
    }
    asm volatile("cp.async.commit_group;" ::: "memory");
}

static __device__ __forceinline__ void load_frags(
    uint32_t abase, uint32_t bbase, int ks,
    uint32_t af[4][4], uint32_t bf[8][2],
    int a_row, int a_hi, int b_row, int b_hi) {
    #pragma unroll
    for (int im = 0; im < 4; im++) {
        int row = a_row + im * 16;
        uint32_t col = (uint32_t)((ks * 2 + a_hi) ^ (row & 7)) << 4;
        ldsm_x4(af[im], abase + row * 128 + col);
    }
    #pragma unroll
    for (int ng = 0; ng < 4; ng++) {
        int row = b_row + ng * 16;
        uint32_t col = (uint32_t)((ks * 2 + b_hi) ^ (row & 7)) << 4;
        uint32_t t[4];
        ldsm_x4(t, bbase + row * 128 + col);
        bf[2 * ng][0] = t[0]; bf[2 * ng][1] = t[1];
        bf[2 * ng + 1][0] = t[2]; bf[2 * ng + 1][1] = t[3];
    }
}

__global__ __launch_bounds__(128, 3) void k_gemm(float* __restrict__ D) {
    extern __shared__ char smem[];
    const uint32_t sb = smem_u32(smem);
    const int tid = threadIdx.x, wid = tid >> 5, lane = tid & 31;
    const int n0 = blockIdx.x << 7, m0 = blockIdx.y << 7;
    const int wm = (wid >> 1) << 6;       // 0 or 64
    const int wn = (wid & 1) << 6;        // 0 or 64

    load_chunk(sb, sb + T_BYTES, m0, n0, 0, tid);

    uint32_t acc[4][8][2];                // f16x2 accumulators: 64 regs
    #pragma unroll
    for (int im = 0; im < 4; im++)
        #pragma unroll
        for (int jn = 0; jn < 8; jn++) { acc[im][jn][0] = 0u; acc[im][jn][1] = 0u; }

    const int a_row = wm + (lane & 15);
    const int a_hi  = lane >> 4;
    const int b_row = wn + (lane & 7) + (((lane >> 4) & 1) << 3);
    const int b_hi  = (lane >> 3) & 1;

    uint32_t af[2][4][4], bf[2][8][2];

    #pragma unroll 1
    for (int i = 0; i < 8; i++) {
        asm volatile("cp.async.wait_group 0;" ::: "memory");
        __syncthreads();
        if (i + 1 < 8)
            load_chunk(sb + ((i + 1) & 1) * STG_BYTES,
                       sb + ((i + 1) & 1) * STG_BYTES + T_BYTES, m0, n0, (i + 1) * 64, tid);
        const uint32_t abase = sb + (i & 1) * STG_BYTES;
        const uint32_t bbase = abase + T_BYTES;
        load_frags(abase, bbase, 0, af[0], bf[0], a_row, a_hi, b_row, b_hi);
        #pragma unroll
        for (int ks = 0; ks < 4; ks++) {
            if (ks < 3)
                load_frags(abase, bbase, ks + 1, af[(ks + 1) & 1], bf[(ks + 1) & 1],
                           a_row, a_hi, b_row, b_hi);
            #pragma unroll
            for (int im = 0; im < 4; im++)
                #pragma unroll
                for (int jn = 0; jn < 8; jn++)
                    mma16816h(acc[im][jn], af[ks & 1][im], bf[ks & 1][jn]);
        }
    }

    // ---- dist stores (convert f16x2 -> f32x2) ----
    const int g = lane >> 2, tig = lane & 3;
    float* dbase = D + (size_t)(m0 + wm + g) * NCODE + n0 + wn + tig * 2;
    #pragma unroll
    for (int im = 0; im < 4; im++) {
        #pragma unroll
        for (int jn = 0; jn < 8; jn++) {
            float* p = dbase + (size_t)(im * 16) * NCODE + jn * 8;
            *(float2*)p = __half22float2(*(__half2*)&acc[im][jn][0]);
            *(float2*)(p + (size_t)8 * NCODE) = __half22float2(*(__half2*)&acc[im][jn][1]);
        }
    }

    // ---- tmax via RED.MAX ----
    #pragma unroll
    for (int im = 0; im < 4; im++) {
        #pragma unroll
        for (int h = 0; h < 2; h++) {
            __half2 m = *(__half2*)&acc[im][0][h];
            #pragma unroll
            for (int jn = 1; jn < 8; jn++) m = __hmax2(m, *(__half2*)&acc[im][jn][h]);
            float2 f = __half22float2(m);
            float v = fmaxf(f.x, f.y);
            v = fmaxf(v, __shfl_xor_sync(0xffffffffu, v, 1));
            v = fmaxf(v, __shfl_xor_sync(0xffffffffu, v, 2));
            if (tig == 0)
                atomicMax(&g_tmax[(size_t)(m0 + wm + im * 16 + h * 8 + g) * NTILES + blockIdx.x],
                          fmap(v));
        }
    }
}

// ---------------- refine ----------------
#define MAXC 128
__global__ __launch_bounds__(256) void k_refine(
    const float* __restrict__ dist, const float* __restrict__ x,
    const float* __restrict__ e, float* __restrict__ qout, float* __restrict__ iout) {
    const int r = blockIdx.x, tid = threadIdx.x;
    const int lane = tid & 31, wid = tid >> 5;

    __shared__ float tmaxs[NTILES];
    __shared__ float thr_s;
    __shared__ int clist[MAXC];
    __shared__ int ccnt;
    if (tid < NTILES) tmaxs[tid] = funmap(g_tmax[(size_t)r * NTILES + tid]);
    __syncthreads();
    if (tid < 32) {
        float v = fmaxf(tmaxs[tid], tmaxs[tid + 32]);
        #pragma unroll
        for (int o = 16; o; o >>= 1) v = fmaxf(v, __shfl_xor_sync(0xffffffffu, v, o));
        if (tid == 0) { thr_s = v - 0.008f; ccnt = 0; }
    }
    __syncthreads();
    const float thr = thr_s;

    const float* drow = dist + (size_t)r * NCODE;
    for (int t = 0; t < NTILES; t++) {
        if (tmaxs[t] >= thr && tid < NTILE) {
            float v = drow[t * NTILE + tid];
            if (v >= thr) {
                int p = atomicAdd(&ccnt, 1);
                if (p < MAXC) clist[p] = t * NTILE + tid;
            }
        }
    }
    __syncthreads();
    const int nc = min(ccnt, MAXC);

    __shared__ double cval[MAXC];
    __shared__ float cinv[MAXC];
    const float* xr = x + (size_t)r * DDIM;
    for (int cI = wid; cI < nc; cI += 8) {
        const float* er = e + (size_t)clist[cI] * DDIM;
        float s = 0.f, comp = 0.f, es = 0.f, ecomp = 0.f;
        for (int k = lane; k < DDIM; k += 32) {
            float a = xr[k], b = er[k];
            float p = __fmul_rn(a, b);
            float pe = __fmaf_rn(a, b, -p);
            float t = __fadd_rn(s, p);
            float z = __fsub_rn(t, s);
            comp = __fadd_rn(comp, __fadd_rn(__fsub_rn(s, __fsub_rn(t, z)), __fsub_rn(p, z)));
            s = t; comp = __fadd_rn(comp, pe);
            float q2 = __fmul_rn(b, b);
            float qe = __fmaf_rn(b, b, -q2);
            float t2 = __fadd_rn(es, q2);
            float z2 = __fsub_rn(t2, es);
            ecomp = __fadd_rn(ecomp, __fadd_rn(__fsub_rn(es, __fsub_rn(t2, z2)), __fsub_rn(q2, z2)));
            es = t2; ecomp = __fadd_rn(ecomp, qe);
        }
        double ds = (double)s + (double)comp;
        double de = (double)es + (double)ecomp;
        #pragma unroll
        for (int o = 16; o; o >>= 1) {
            ds += __shfl_down_sync(0xffffffffu, ds, o);
            de += __shfl_down_sync(0xffffffffu, de, o);
        }
        if (lane == 0) {
            double ne = sqrt(de);
            cval[cI] = ds / ne;
            cinv[cI] = (float)(1.0 / (ne > 1e-12 ? ne : 1e-12));
        }
    }
    __syncthreads();
    __shared__ int wcol_s;
    __shared__ float winv_s;
    if (tid == 0) {
        double best = -1e300; int bc = 0x7fffffff; float bi = 0.f;
        for (int c = 0; c < nc; c++) {
            double v = cval[c]; int col = clist[c];
            if (v > best || (v == best && col < bc)) { best = v; bc = col; bi = cinv[c]; }
        }
        wcol_s = bc; winv_s = bi;
        iout[r] = (float)bc;
    }
    __syncthreads();
    const float* ew = e + (size_t)wcol_s * DDIM;
    const float wi = winv_s;
    qout[(size_t)r * DDIM + tid]       = ew[tid] * wi;
    qout[(size_t)r * DDIM + tid + 256] = ew[tid + 256] * wi;
}

// ---------------- launch ----------------
extern "C" void kernel_launch(void* const* d_in, const int* in_sizes, int n_in,
                              void* d_out, int out_size) {
    (void)in_sizes; (void)n_in; (void)out_size;
    const float* x = (const float*)d_in[0];
    const float* e = (const float*)d_in[1];
    float* qout = (float*)d_out;
    float* iout = qout + (size_t)NROWS * DDIM;
    float* dist = iout + NROWS;

    cudaFuncSetAttribute(k_gemm, cudaFuncAttributeMaxDynamicSharedMemorySize, GEMM_SMEM);
    k_norm<<<NROWS + NCODE, 128>>>(x, e);
    dim3 gg(NCODE / 128, NROWS / 128);
    k_gemm<<<gg, 128, GEMM_SMEM>>>(dist);
    k_refine<<<NROWS, 256>>>(dist, x, e, qout, iout);
}

// round 13
// speedup vs baseline: 1.3430x; 1.2209x over previous
#include <cuda_runtime.h>
#include <cuda_fp16.h>
#include <cstdint>

#define NROWS 16384
#define NCODE 8192
#define DDIM  512
#define NTILE 128
#define NTILES (NCODE / NTILE)   /* 64 */

__device__ __half g_xh[(size_t)NROWS * DDIM];
__device__ __half g_eh[(size_t)NCODE * DDIM];
__device__ unsigned g_tmax[(size_t)NROWS * NTILES];   // order-mapped floats; 0 = identity

// ---------------- helpers ----------------
static __device__ __forceinline__ uint32_t smem_u32(const void* p) {
    uint32_t a;
    asm("{ .reg .u64 t; cvta.to.shared.u64 t, %1; cvt.u32.u64 %0, t; }" : "=r"(a) : "l"(p));
    return a;
}
static __device__ __forceinline__ void cp16(uint32_t dst, const void* src) {
    asm volatile("cp.async.cg.shared.global [%0], [%1], 16;"
                 :: "r"(dst), "l"(__cvta_generic_to_global(src)));
}
static __device__ __forceinline__ void ldsm_x4(uint32_t* r, uint32_t addr) {
    asm volatile("ldmatrix.sync.aligned.m8n8.x4.shared.b16 {%0,%1,%2,%3}, [%4];"
                 : "=r"(r[0]), "=r"(r[1]), "=r"(r[2]), "=r"(r[3]) : "r"(addr));
}
static __device__ __forceinline__ void mma16816h(uint32_t* d, const uint32_t* a, const uint32_t* b) {
    asm volatile(
        "mma.sync.aligned.m16n8k16.row.col.f16.f16.f16.f16 "
        "{%0,%1},{%2,%3,%4,%5},{%6,%7},{%0,%1};"
        : "+r"(d[0]), "+r"(d[1])
        : "r"(a[0]), "r"(a[1]), "r"(a[2]), "r"(a[3]), "r"(b[0]), "r"(b[1]));
}
static __device__ __forceinline__ unsigned fmap(float v) {
    int i = __float_as_int(v);
    return (unsigned)i ^ (unsigned)((i >> 31) | 0x80000000);
}
static __device__ __forceinline__ float funmap(unsigned k) {
    int i = (k & 0x80000000u) ? (int)(k ^ 0x80000000u) : (int)~k;
    return __int_as_float(i);
}

// ---------------- normalize rows -> f16 (+ clear g_tmax) ----------------
__global__ __launch_bounds__(128) void k_norm(const float* __restrict__ x,
                                              const float* __restrict__ e) {
    const int b = blockIdx.x, tid = threadIdx.x;
    const float* in;
    __half* out;
    if (b < NROWS) {
        in = x + (size_t)b * DDIM; out = g_xh + (size_t)b * DDIM;
        if (tid < NTILES) g_tmax[(size_t)b * NTILES + tid] = 0u;
    } else {
        in = e + (size_t)(b - NROWS) * DDIM; out = g_eh + (size_t)(b - NROWS) * DDIM;
    }
    const float4 v = ((const float4*)in)[tid];
    float ss = v.x * v.x + v.y * v.y + v.z * v.z + v.w * v.w;
    #pragma unroll
    for (int o = 16; o; o >>= 1) ss += __shfl_down_sync(0xffffffffu, ss, o);
    __shared__ float sred[4];
    if ((tid & 31) == 0) sred[tid >> 5] = ss;
    __syncthreads();
    if (tid == 0) {
        float t = sred[0] + sred[1] + sred[2] + sred[3];
        sred[0] = 1.0f / fmaxf(sqrtf(t), 1e-12f);
    }
    __syncthreads();
    const float sc = sred[0];
    __half2* oh = (__half2*)out;
    oh[tid * 2]     = __floats2half2_rn(v.x * sc, v.y * sc);
    oh[tid * 2 + 1] = __floats2half2_rn(v.z * sc, v.w * sc);
}

// ---------------- mma.sync GEMM (f16 acc) — unchanged from R12 ----------------
#define T_BYTES (128 * 128)
#define STG_BYTES (2 * T_BYTES)
#define GEMM_SMEM (2 * STG_BYTES)       /* 64 KB */

static __device__ __forceinline__ void load_chunk(uint32_t abase, uint32_t bbase,
                                                  int m0, int n0, int k0, int tid) {
    #pragma unroll
    for (int i = 0; i < 8; i++) {
        int idx = tid + (i << 7);
        int row = idx >> 3, g = idx & 7;
        uint32_t dst = (uint32_t)(row * 128) + ((uint32_t)(g ^ (row & 7)) << 4);
        cp16(abase + dst, g_xh + (size_t)(m0 + row) * DDIM + k0 + g * 8);
        cp16(bbase + dst, g_eh + (size_t)(n0 + row) * DDIM + k0 + g * 8);
    }
    asm volatile("cp.async.commit_group;" ::: "memory");
}

static __device__ __forceinline__ void load_frags(
    uint32_t abase, uint32_t bbase, int ks,
    uint32_t af[4][4], uint32_t bf[8][2],
    int a_row, int a_hi, int b_row, int b_hi) {
    #pragma unroll
    for (int im = 0; im < 4; im++) {
        int row = a_row + im * 16;
        uint32_t col = (uint32_t)((ks * 2 + a_hi) ^ (row & 7)) << 4;
        ldsm_x4(af[im], abase + row * 128 + col);
    }
    #pragma unroll
    for (int ng = 0; ng < 4; ng++) {
        int row = b_row + ng * 16;
        uint32_t col = (uint32_t)((ks * 2 + b_hi) ^ (row & 7)) << 4;
        uint32_t t[4];
        ldsm_x4(t, bbase + row * 128 + col);
        bf[2 * ng][0] = t[0]; bf[2 * ng][1] = t[1];
        bf[2 * ng + 1][0] = t[2]; bf[2 * ng + 1][1] = t[3];
    }
}

__global__ __launch_bounds__(128, 3) void k_gemm(float* __restrict__ D) {
    extern __shared__ char smem[];
    const uint32_t sb = smem_u32(smem);
    const int tid = threadIdx.x, wid = tid >> 5, lane = tid & 31;
    const int n0 = blockIdx.x << 7, m0 = blockIdx.y << 7;
    const int wm = (wid >> 1) << 6;
    const int wn = (wid & 1) << 6;

    load_chunk(sb, sb + T_BYTES, m0, n0, 0, tid);

    uint32_t acc[4][8][2];
    #pragma unroll
    for (int im = 0; im < 4; im++)
        #pragma unroll
        for (int jn = 0; jn < 8; jn++) { acc[im][jn][0] = 0u; acc[im][jn][1] = 0u; }

    const int a_row = wm + (lane & 15);
    const int a_hi  = lane >> 4;
    const int b_row = wn + (lane & 7) + (((lane >> 4) & 1) << 3);
    const int b_hi  = (lane >> 3) & 1;

    uint32_t af[2][4][4], bf[2][8][2];

    #pragma unroll 1
    for (int i = 0; i < 8; i++) {
        asm volatile("cp.async.wait_group 0;" ::: "memory");
        __syncthreads();
        if (i + 1 < 8)
            load_chunk(sb + ((i + 1) & 1) * STG_BYTES,
                       sb + ((i + 1) & 1) * STG_BYTES + T_BYTES, m0, n0, (i + 1) * 64, tid);
        const uint32_t abase = sb + (i & 1) * STG_BYTES;
        const uint32_t bbase = abase + T_BYTES;
        load_frags(abase, bbase, 0, af[0], bf[0], a_row, a_hi, b_row, b_hi);
        #pragma unroll
        for (int ks = 0; ks < 4; ks++) {
            if (ks < 3)
                load_frags(abase, bbase, ks + 1, af[(ks + 1) & 1], bf[(ks + 1) & 1],
                           a_row, a_hi, b_row, b_hi);
            #pragma unroll
            for (int im = 0; im < 4; im++)
                #pragma unroll
                for (int jn = 0; jn < 8; jn++)
                    mma16816h(acc[im][jn], af[ks & 1][im], bf[ks & 1][jn]);
        }
    }

    const int g = lane >> 2, tig = lane & 3;
    float* dbase = D + (size_t)(m0 + wm + g) * NCODE + n0 + wn + tig * 2;
    #pragma unroll
    for (int im = 0; im < 4; im++) {
        #pragma unroll
        for (int jn = 0; jn < 8; jn++) {
            float* p = dbase + (size_t)(im * 16) * NCODE + jn * 8;
            *(float2*)p = __half22float2(*(__half2*)&acc[im][jn][0]);
            *(float2*)(p + (size_t)8 * NCODE) = __half22float2(*(__half2*)&acc[im][jn][1]);
        }
    }

    #pragma unroll
    for (int im = 0; im < 4; im++) {
        #pragma unroll
        for (int h = 0; h < 2; h++) {
            __half2 m = *(__half2*)&acc[im][0][h];
            #pragma unroll
            for (int jn = 1; jn < 8; jn++) m = __hmax2(m, *(__half2*)&acc[im][jn][h]);
            float2 f = __half22float2(m);
            float v = fmaxf(f.x, f.y);
            v = fmaxf(v, __shfl_xor_sync(0xffffffffu, v, 1));
            v = fmaxf(v, __shfl_xor_sync(0xffffffffu, v, 2));
            if (tig == 0)
                atomicMax(&g_tmax[(size_t)(m0 + wm + im * 16 + h * 8 + g) * NTILES + blockIdx.x],
                          fmap(v));
        }
    }
}

// ---------------- refine v2: one warp per row, no block syncs ----------------
#define MAXC 32
__global__ __launch_bounds__(256) void k_refine(
    const float* __restrict__ dist, const float* __restrict__ x,
    const float* __restrict__ e, float* __restrict__ qout, float* __restrict__ iout) {
    const int warp = threadIdx.x >> 5, lane = threadIdx.x & 31;
    const int r = blockIdx.x * 8 + warp;

    // threshold from tile maxes
    const float t0 = funmap(g_tmax[(size_t)r * NTILES + lane]);
    const float t1 = funmap(g_tmax[(size_t)r * NTILES + 32 + lane]);
    float m = fmaxf(t0, t1);
    #pragma unroll
    for (int o = 16; o; o >>= 1) m = fmaxf(m, __shfl_xor_sync(0xffffffffu, m, o));
    const float thr = m - 0.008f;

    __shared__ int s_cols[8][MAXC];
    __shared__ int s_cnt[8];
    __shared__ double s_val[8][MAXC];
    __shared__ float s_inv[8][MAXC];
    if (lane == 0) s_cnt[warp] = 0;
    __syncwarp();

    // candidate scan over qualifying tiles
    const float* drow = dist + (size_t)r * NCODE;
    for (int t = 0; t < NTILES; t++) {
        float tm = __shfl_sync(0xffffffffu, (t < 32) ? t0 : t1, t & 31);
        if (tm >= thr) {
            float4 v = ((const float4*)(drow + t * NTILE))[lane];
            int c0 = t * NTILE + lane * 4;
            if (v.x >= thr) { int p = atomicAdd(&s_cnt[warp], 1); if (p < MAXC) s_cols[warp][p] = c0; }
            if (v.y >= thr) { int p = atomicAdd(&s_cnt[warp], 1); if (p < MAXC) s_cols[warp][p] = c0 + 1; }
            if (v.z >= thr) { int p = atomicAdd(&s_cnt[warp], 1); if (p < MAXC) s_cols[warp][p] = c0 + 2; }
            if (v.w >= thr) { int p = atomicAdd(&s_cnt[warp], 1); if (p < MAXC) s_cols[warp][p] = c0 + 3; }
        }
    }
    __syncwarp();
    const int nc = min(s_cnt[warp], MAXC);

    // exact rescore (compensated fp32), whole warp per candidate
    const float* xr = x + (size_t)r * DDIM;
    for (int cI = 0; cI < nc; cI++) {
        const float* er = e + (size_t)s_cols[warp][cI] * DDIM;
        float s = 0.f, comp = 0.f, es = 0.f, ecomp = 0.f;
        #pragma unroll
        for (int k = lane; k < DDIM; k += 32) {
            float a = xr[k], b = er[k];
            float p = __fmul_rn(a, b);
            float pe = __fmaf_rn(a, b, -p);
            float t = __fadd_rn(s, p);
            float z = __fsub_rn(t, s);
            comp = __fadd_rn(comp, __fadd_rn(__fsub_rn(s, __fsub_rn(t, z)), __fsub_rn(p, z)));
            s = t; comp = __fadd_rn(comp, pe);
            float q2 = __fmul_rn(b, b);
            float qe = __fmaf_rn(b, b, -q2);
            float t2 = __fadd_rn(es, q2);
            float z2 = __fsub_rn(t2, es);
            ecomp = __fadd_rn(ecomp, __fadd_rn(__fsub_rn(es, __fsub_rn(t2, z2)), __fsub_rn(q2, z2)));
            es = t2; ecomp = __fadd_rn(ecomp, qe);
        }
        double ds = (double)s + (double)comp;
        double de = (double)es + (double)ecomp;
        #pragma unroll
        for (int o = 16; o; o >>= 1) {
            ds += __shfl_down_sync(0xffffffffu, ds, o);
            de += __shfl_down_sync(0xffffffffu, de, o);
        }
        if (lane == 0) {
            double ne = sqrt(de);
            s_val[warp][cI] = ds / ne;
            s_inv[warp][cI] = (float)(1.0 / (ne > 1e-12 ? ne : 1e-12));
        }
    }
    __syncwarp();

    // winner
    int bc = 0; float bi = 0.f;
    if (lane == 0) {
        double best = -1e300; bc = 0x7fffffff;
        for (int c = 0; c < nc; c++) {
            double v = s_val[warp][c]; int col = s_cols[warp][c];
            if (v > best || (v == best && col < bc)) { best = v; bc = col; bi = s_inv[warp][c]; }
        }
        iout[r] = (float)bc;
    }
    bc = __shfl_sync(0xffffffffu, bc, 0);
    bi = __shfl_sync(0xffffffffu, bi, 0);

    // quantize row = normalized codebook row
    const float4* ew = (const float4*)(e + (size_t)bc * DDIM);
    float4* qo = (float4*)(qout + (size_t)r * DDIM);
    #pragma unroll
    for (int q = lane; q < DDIM / 4; q += 32) {
        float4 v = ew[q];
        qo[q] = make_float4(v.x * bi, v.y * bi, v.z * bi, v.w * bi);
    }
}

// ---------------- launch ----------------
extern "C" void kernel_launch(void* const* d_in, const int* in_sizes, int n_in,
                              void* d_out, int out_size) {
    (void)in_sizes; (void)n_in; (void)out_size;
    const float* x = (const float*)d_in[0];
    const float* e = (const float*)d_in[1];
    float* qout = (float*)d_out;
    float* iout = qout + (size_t)NROWS * DDIM;
    float* dist = iout + NROWS;

    cudaFuncSetAttribute(k_gemm, cudaFuncAttributeMaxDynamicSharedMemorySize, GEMM_SMEM);
    k_norm<<<NROWS + NCODE, 128>>>(x, e);
    dim3 gg(NCODE / 128, NROWS / 128);
    k_gemm<<<gg, 128, GEMM_SMEM>>>(dist);
    k_refine<<<NROWS / 8, 256>>>(dist, x, e, qout, iout);
}